// round 15
// baseline (speedup 1.0000x reference)
#include <cuda_runtime.h>

#define BB 16
#define NN 4096
#define SS 1024
#define KK 32
#define POSN (BB*SS*KK)          // 524288
#define NGRP (BB*SS)             // 16384
#define XYZ_OUT (BB*3*SS)        // 49152

typedef unsigned long long ull;

// ---------------- packed f32x2 helpers ----------------
union U2 { ull u; float2 f; };

__device__ __forceinline__ ull pack2(float lo, float hi) {
    U2 t; t.f.x = lo; t.f.y = hi; return t.u;
}
__device__ __forceinline__ void ffma2(ull& d, ull a, ull b) {
    asm("fma.rn.f32x2 %0, %1, %2, %0;" : "+l"(d) : "l"(a), "l"(b));
}
__device__ __forceinline__ ull add2(ull a, ull b) {
    ull r; asm("add.rn.f32x2 %0, %1, %2;" : "=l"(r) : "l"(a), "l"(b)); return r;
}
__device__ __forceinline__ ull mul2(ull a, ull b) {
    ull r; asm("mul.rn.f32x2 %0, %1, %2;" : "=l"(r) : "l"(a), "l"(b)); return r;
}
__device__ __forceinline__ ull max2(ull a, ull b) {
    U2 x, y, r; x.u = a; y.u = b;
    r.f.x = fmaxf(x.f.x, y.f.x); r.f.y = fmaxf(x.f.y, y.f.y);
    return r.u;
}
__device__ __forceinline__ ull min2(ull a, ull b) {
    U2 x, y, r; x.u = a; y.u = b;
    r.f.x = fminf(x.f.x, y.f.x); r.f.y = fminf(x.f.y, y.f.y);
    return r.u;
}
__device__ __forceinline__ ull umax64(ull a, ull b) { return a > b ? a : b; }

// ---------------- scratch ----------------
__device__ float g_newxyz[BB][SS][3];
__device__ float g_G[6][POSN];
__device__ float g_x1[64][POSN];
__device__ float g_m2[NGRP][128];
__device__ float g_gsum0[6], g_gram0[21];
__device__ float g_sum1[64], g_sq1[64];
__device__ float g_sum2[128], g_sq2[128];
__device__ float g_s0[64], g_t0[64];
__device__ float g_s1[64], g_t1[64];
__device__ float g_s2[128], g_t2[128];

// ---------------- tiny kernels ----------------
__global__ void zero_kernel() {
    int t = threadIdx.x;
    if (t < 64) { g_sum1[t] = 0.f; g_sq1[t] = 0.f; }
    if (t < 128) { g_sum2[t] = 0.f; g_sq2[t] = 0.f; }
    if (t < 6) g_gsum0[t] = 0.f;
    if (t < 21) g_gram0[t] = 0.f;
}

// ---------------- FPS: R9 base + 3-level key tree in the tail ----------------
__global__ __launch_bounds__(256) void fps_kernel(const float* __restrict__ xyz,
                                                  float* __restrict__ out) {
    __shared__ ull s_key[2][8];
    __shared__ int s_idx[SS];

    const int b = blockIdx.x;
    const int tid = threadIdx.x;
    const int w = tid >> 5, lane = tid & 31;
    const float* px = xyz + (size_t)b * 3 * NN;
    const float* py = px + NN;
    const float* pz = px + 2 * NN;

    const int base = tid * 16;
    ull X2[8], Y2[8], Z2[8], D2[8];
#pragma unroll
    for (int j = 0; j < 8; j++) {
        X2[j] = *(const ull*)(px + base + 2 * j);
        Y2[j] = *(const ull*)(py + base + 2 * j);
        Z2[j] = *(const ull*)(pz + base + 2 * j);
        D2[j] = pack2(1e10f, 1e10f);
    }

    int cur = 0;
    for (int it = 0; it < SS; it++) {
        if (tid == 0) s_idx[it] = cur;
        float cx = px[cur], cy = py[cur], cz = pz[cur];
        ull ncx = pack2(-cx, -cx), ncy = pack2(-cy, -cy), ncz = pack2(-cz, -cz);

        ull bm = pack2(-1.0f, -1.0f);
#pragma unroll
        for (int j = 0; j < 8; j++) {
            ull dx = add2(X2[j], ncx);
            ull dy = add2(Y2[j], ncy);
            ull dz = add2(Z2[j], ncz);
            ull t = mul2(dx, dx);
            ffma2(t, dy, dy);
            ffma2(t, dz, dz);
            D2[j] = min2(D2[j], t);
            bm = max2(bm, D2[j]);
        }
        U2 bu; bu.u = bm;
        float bv = fmaxf(bu.f.x, bu.f.y);
        unsigned wmx = __reduce_max_sync(0xffffffffu, __float_as_uint(bv));
        float wmax = __uint_as_float(wmx);
        int cand = 0x7fffffff;
#pragma unroll
        for (int j = 7; j >= 0; j--) {          // descending => smallest index survives
            U2 d; d.u = D2[j];
            if (d.f.y == wmax) cand = base + 2 * j + 1;
            if (d.f.x == wmax) cand = base + 2 * j;
        }
        unsigned m = __ballot_sync(0xffffffffu, cand != 0x7fffffff);
        int widx = __shfl_sync(0xffffffffu, cand, __ffs(m) - 1);
        if (lane == 0)
            s_key[it & 1][w] = (((ull)wmx) << 32) | (unsigned)(~widx);
        __syncthreads();                         // the ONLY barrier per iteration
        // balanced 3-level max tree over the 8 warp keys (shorter dep chain)
        ull a0 = s_key[it & 1][0], a1 = s_key[it & 1][1];
        ull a2 = s_key[it & 1][2], a3 = s_key[it & 1][3];
        ull a4 = s_key[it & 1][4], a5 = s_key[it & 1][5];
        ull a6 = s_key[it & 1][6], a7 = s_key[it & 1][7];
        ull k01 = umax64(a0, a1), k23 = umax64(a2, a3);
        ull k45 = umax64(a4, a5), k67 = umax64(a6, a7);
        ull k03 = umax64(k01, k23), k47 = umax64(k45, k67);
        ull k = umax64(k03, k47);
        cur = (int)(~(unsigned)k);               // all threads agree
    }

    for (int s = tid; s < SS; s += 256) {
        int i = s_idx[s];
        float cx = px[i], cy = py[i], cz = pz[i];
        g_newxyz[b][s][0] = cx; g_newxyz[b][s][1] = cy; g_newxyz[b][s][2] = cz;
        out[(size_t)b * 3 * SS + s]          = cx;
        out[(size_t)b * 3 * SS + SS + s]     = cy;
        out[(size_t)b * 3 * SS + 2 * SS + s] = cz;
    }
}

// ---------------- ball query + grouping: R13 2-chunk scan (measured 56.8us) ----------------
__global__ __launch_bounds__(256) void ball_group_kernel(const float* __restrict__ xyz,
                                                         const float* __restrict__ feat) {
    __shared__ int nbr[8][KK];
    const int tid = threadIdx.x;
    const int w = tid >> 5, lane = tid & 31;
    const int gw = blockIdx.x * 8 + w;
    const int b = gw >> 10, s = gw & 1023;

    const float* px = xyz + (size_t)b * 3 * NN;
    const float* py = px + NN;
    const float* pz = px + 2 * NN;

    const float cx = g_newxyz[b][s][0];
    const float cy = g_newxyz[b][s][1];
    const float cz = g_newxyz[b][s][2];
    const float sn = __fadd_rn(__fadd_rn(__fmul_rn(cx, cx), __fmul_rn(cy, cy)),
                               __fmul_rn(cz, cz));

    int cnt = 0;
    for (int c0 = 0; c0 < NN && cnt < KK; c0 += 64) {
        int n0 = c0 + lane;
        int n1 = c0 + 32 + lane;
        float x0 = px[n0], y0 = py[n0], z0 = pz[n0];
        float x1 = px[n1], y1 = py[n1], z1 = pz[n1];
        float xn0 = __fadd_rn(__fadd_rn(__fmul_rn(x0, x0), __fmul_rn(y0, y0)),
                              __fmul_rn(z0, z0));
        float xn1 = __fadd_rn(__fadd_rn(__fmul_rn(x1, x1), __fmul_rn(y1, y1)),
                              __fmul_rn(z1, z1));
        float dt0 = __fadd_rn(__fadd_rn(__fmul_rn(cx, x0), __fmul_rn(cy, y0)),
                              __fmul_rn(cz, z0));
        float dt1 = __fadd_rn(__fadd_rn(__fmul_rn(cx, x1), __fmul_rn(cy, y1)),
                              __fmul_rn(cz, z1));
        float sqr0 = __fsub_rn(__fadd_rn(sn, xn0), __fmul_rn(2.0f, dt0));
        float sqr1 = __fsub_rn(__fadd_rn(sn, xn1), __fmul_rn(2.0f, dt1));
        bool in0 = !(sqr0 > 0.04f);
        bool in1 = !(sqr1 > 0.04f);
        unsigned m0 = __ballot_sync(0xffffffffu, in0);
        unsigned m1 = __ballot_sync(0xffffffffu, in1);
        if (in0) {
            int slot = cnt + __popc(m0 & ((1u << lane) - 1u));
            if (slot < KK) nbr[w][slot] = n0;
        }
        cnt += __popc(m0);
        if (in1) {
            int slot = cnt + __popc(m1 & ((1u << lane) - 1u));
            if (slot < KK) nbr[w][slot] = n1;
        }
        cnt += __popc(m1);
    }
    __syncwarp();
    int eff = cnt < KK ? cnt : KK;
    int first = nbr[w][0];
    int myn = (lane < eff) ? nbr[w][lane] : first;

    float gx = px[myn] - cx, gy = py[myn] - cy, gz = pz[myn] - cz;
    const float* f = feat + (size_t)b * 3 * NN;
    float f0 = f[myn], f1 = f[NN + myn], f2 = f[2 * NN + myn];

    size_t pos = ((size_t)gw) * KK + lane;
    g_G[0][pos] = gx; g_G[1][pos] = gy; g_G[2][pos] = gz;
    g_G[3][pos] = f0; g_G[4][pos] = f1; g_G[5][pos] = f2;
}

// ---------------- Gram: 512 blocks x 4 iters (was 128x16, latency-bound) ----------------
__global__ __launch_bounds__(256) void gram_kernel() {
    const int tid = threadIdx.x;
    const int lane = tid & 31;
    size_t p0 = (size_t)blockIdx.x * 1024 + tid;
    float S[6] = {0, 0, 0, 0, 0, 0};
    float G[21];
#pragma unroll
    for (int k = 0; k < 21; k++) G[k] = 0.f;

#pragma unroll
    for (int itn = 0; itn < 4; itn++) {
        size_t pos = p0 + (size_t)itn * 256;
        float g[6];
#pragma unroll
        for (int c = 0; c < 6; c++) g[c] = g_G[c][pos];
        int k = 0;
#pragma unroll
        for (int c = 0; c < 6; c++) {
            S[c] += g[c];
#pragma unroll
            for (int d = c; d < 6; d++) { G[k] = fmaf(g[c], g[d], G[k]); k++; }
        }
    }
#pragma unroll
    for (int o = 16; o > 0; o >>= 1) {
#pragma unroll
        for (int c = 0; c < 6; c++) S[c] += __shfl_xor_sync(0xffffffffu, S[c], o);
#pragma unroll
        for (int k = 0; k < 21; k++) G[k] += __shfl_xor_sync(0xffffffffu, G[k], o);
    }
    if (lane == 0) {
#pragma unroll
        for (int c = 0; c < 6; c++) atomicAdd(&g_gsum0[c], S[c]);
#pragma unroll
        for (int k = 0; k < 21; k++) atomicAdd(&g_gram0[k], G[k]);
    }
}

// ---------------- stats0: BN affine from Gram quadratic form ----------------
__global__ void stats0_kernel(const float* __restrict__ W,
                              const float* __restrict__ gamma,
                              const float* __restrict__ beta) {
    int c = threadIdx.x;
    if (c >= 64) return;
    float w[6];
#pragma unroll
    for (int i = 0; i < 6; i++) w[i] = W[c * 6 + i];

    float sum = 0.f;
#pragma unroll
    for (int i = 0; i < 6; i++) sum = fmaf(w[i], g_gsum0[i], sum);

    float sq = 0.f;
    int k = 0;
#pragma unroll
    for (int i = 0; i < 6; i++)
#pragma unroll
        for (int j = i; j < 6; j++) {
            float coef = (i == j) ? w[i] * w[i] : 2.0f * w[i] * w[j];
            sq = fmaf(coef, g_gram0[k], sq);
            k++;
        }

    const float inv = 1.0f / (float)POSN;
    float mu = sum * inv;
    float var = fmaf(-mu, mu, sq * inv);
    if (var < 0.f) var = 0.f;
    float rs = 1.0f / sqrtf(var + 1e-5f);
    float sc = rs * gamma[c];
    g_s0[c] = sc;
    g_t0[c] = fmaf(-mu, sc, beta[c]);
}

// ---------------- stats (stages 1,2) ----------------
template <int STAGE>
__global__ void stats_kernel(const float* __restrict__ gamma, const float* __restrict__ beta) {
    constexpr int C = (STAGE == 2) ? 128 : 64;
    const float* sum = STAGE == 1 ? g_sum1 : g_sum2;
    const float* sq  = STAGE == 1 ? g_sq1  : g_sq2;
    float* Sv = STAGE == 1 ? g_s1 : g_s2;
    float* Tv = STAGE == 1 ? g_t1 : g_t2;
    int c = threadIdx.x;
    if (c < C) {
        const float inv = 1.0f / (float)POSN;
        float m = sum[c] * inv;
        float var = fmaf(-m, m, sq[c] * inv);
        if (var < 0.f) var = 0.f;
        float rs = 1.0f / sqrtf(var + 1e-5f);
        float sc = rs * gamma[c];
        Sv[c] = sc;
        Tv[c] = fmaf(-m, sc, beta[c]);
    }
}

// ---------------- gemm1: R12 version (LDS.64-direct weights) — UNCHANGED ----------------
__global__ __launch_bounds__(256) void gemm1_kernel(const float* __restrict__ W0,
                                                    const float* __restrict__ W1) {
    __shared__ __align__(16) float w0s[6 * 64];     // w0s[i*64+o]
    __shared__ __align__(16) float Wp[64 * 32];     // per-pass: Wp[i*32+o]
    __shared__ float ss[64], tt[64];
    __shared__ float tile[8][32][33];
    __shared__ float s_sum[64], s_sq[64];
    const int tid = threadIdx.x;
    const int w = tid >> 5, lane = tid & 31;
    for (int e = tid; e < 384; e += 256) {
        int i = e >> 6, o = e & 63;
        w0s[e] = W0[o * 6 + i];
    }
    if (tid < 64) {
        ss[tid] = g_s0[tid]; tt[tid] = g_t0[tid];
        s_sum[tid] = 0.f; s_sq[tid] = 0.f;
    }
    __syncthreads();

    size_t pos = (size_t)blockIdx.x * 256 + tid;
    float g[6];
#pragma unroll
    for (int c = 0; c < 6; c++) g[c] = g_G[c][pos];

    ull acc0[32];
#pragma unroll
    for (int o2 = 0; o2 < 32; o2++) acc0[o2] = 0ull;
#pragma unroll
    for (int i = 0; i < 6; i++) {
        ull g2 = pack2(g[i], g[i]);
        const ull* wr = (const ull*)(w0s + i * 64);
#pragma unroll
        for (int o2 = 0; o2 < 32; o2++) ffma2(acc0[o2], wr[o2], g2);
    }
    float y[64];
#pragma unroll
    for (int o2 = 0; o2 < 32; o2++) {
        U2 u; u.u = acc0[o2];
        y[2 * o2]     = fmaxf(fmaf(ss[2 * o2],     u.f.x, tt[2 * o2]),     0.0f);
        y[2 * o2 + 1] = fmaxf(fmaf(ss[2 * o2 + 1], u.f.y, tt[2 * o2 + 1]), 0.0f);
    }

#pragma unroll 1
    for (int pass = 0; pass < 2; pass++) {
        __syncthreads();
        for (int e = tid; e < 2048; e += 256) {
            int i = e >> 5, o = e & 31;
            Wp[e] = W1[(pass * 32 + o) * 64 + i];
        }
        __syncthreads();

        ull acc2[16];
#pragma unroll
        for (int jp = 0; jp < 16; jp++) acc2[jp] = 0ull;
#pragma unroll 8
        for (int i = 0; i < 64; i++) {
            ull y2 = pack2(y[i], y[i]);
            const ull* wv = (const ull*)(Wp + i * 32);  // LDS.64 pre-paired operands
#pragma unroll
            for (int jp = 0; jp < 16; jp++) ffma2(acc2[jp], wv[jp], y2);
        }
#pragma unroll
        for (int jp = 0; jp < 16; jp++) {
            U2 u; u.u = acc2[jp];
            int c0 = pass * 32 + 2 * jp;
            g_x1[c0][pos]     = u.f.x;
            g_x1[c0 + 1][pos] = u.f.y;
            tile[w][lane][2 * jp]     = u.f.x;
            tile[w][lane][2 * jp + 1] = u.f.y;
        }
        __syncwarp();
        if (lane < 16) {
            float sm0 = 0.f, sm1 = 0.f, q0 = 0.f, q1 = 0.f;
#pragma unroll 8
            for (int r = 0; r < 32; r++) {
                float v0 = tile[w][r][2 * lane];
                float v1 = tile[w][r][2 * lane + 1];
                sm0 += v0; q0 = fmaf(v0, v0, q0);
                sm1 += v1; q1 = fmaf(v1, v1, q1);
            }
            int c0 = pass * 32 + 2 * lane;
            atomicAdd(&s_sum[c0], sm0);     atomicAdd(&s_sum[c0 + 1], sm1);
            atomicAdd(&s_sq[c0], q0);       atomicAdd(&s_sq[c0 + 1], q1);
        }
        __syncwarp();
    }
    __syncthreads();
    if (tid < 64) {
        atomicAdd(&g_sum1[tid], s_sum[tid]);
        atomicAdd(&g_sq1[tid], s_sq[tid]);
    }
}

// ---------------- gemm2: R12 version (LDS.64-direct weights) — UNCHANGED ----------------
__global__ __launch_bounds__(256) void gemm2_kernel(const float* __restrict__ W) {
    __shared__ __align__(16) float Wp[64 * 32];
    __shared__ float ss[64], tt[64];
    __shared__ float tile[8][32][33];
    __shared__ float s_sum[128], s_sq[128];
    const int tid = threadIdx.x;
    const int w = tid >> 5, lane = tid & 31;
    if (tid < 64) { ss[tid] = g_s1[tid]; tt[tid] = g_t1[tid]; }
    if (tid < 128) { s_sum[tid] = 0.f; s_sq[tid] = 0.f; }
    __syncthreads();

    size_t pos = (size_t)blockIdx.x * 256 + tid;
    const int group = (int)(pos >> 5);
    float y[64];
#pragma unroll
    for (int i = 0; i < 64; i++)
        y[i] = fmaxf(fmaf(ss[i], g_x1[i][pos], tt[i]), 0.0f);

#pragma unroll 1
    for (int pass = 0; pass < 4; pass++) {
        __syncthreads();
        for (int e = tid; e < 2048; e += 256) {
            int i = e >> 5, o = e & 31;
            Wp[e] = W[(pass * 32 + o) * 64 + i];
        }
        __syncthreads();

        ull acc2[16];
#pragma unroll
        for (int jp = 0; jp < 16; jp++) acc2[jp] = 0ull;
#pragma unroll 8
        for (int i = 0; i < 64; i++) {
            ull y2 = pack2(y[i], y[i]);
            const ull* wv = (const ull*)(Wp + i * 32);  // LDS.64 pre-paired operands
#pragma unroll
            for (int jp = 0; jp < 16; jp++) ffma2(acc2[jp], wv[jp], y2);
        }
#pragma unroll
        for (int jp = 0; jp < 16; jp++) {
            U2 u; u.u = acc2[jp];
            tile[w][lane][2 * jp]     = u.f.x;
            tile[w][lane][2 * jp + 1] = u.f.y;
        }
        __syncwarp();
        if (lane < 16) {
            float sm0 = 0.f, sm1 = 0.f, q0 = 0.f, q1 = 0.f;
            float mx0 = -1e30f, mx1 = -1e30f;
#pragma unroll 8
            for (int r = 0; r < 32; r++) {
                float v0 = tile[w][r][2 * lane];
                float v1 = tile[w][r][2 * lane + 1];
                sm0 += v0; q0 = fmaf(v0, v0, q0); mx0 = fmaxf(mx0, v0);
                sm1 += v1; q1 = fmaf(v1, v1, q1); mx1 = fmaxf(mx1, v1);
            }
            int c0 = pass * 32 + 2 * lane;
            atomicAdd(&s_sum[c0], sm0);     atomicAdd(&s_sum[c0 + 1], sm1);
            atomicAdd(&s_sq[c0], q0);       atomicAdd(&s_sq[c0 + 1], q1);
            *(ull*)&g_m2[group][c0] = pack2(mx0, mx1);
        }
        __syncwarp();
    }
    __syncthreads();
    if (tid < 128) {
        atomicAdd(&g_sum2[tid], s_sum[tid]);
        atomicAdd(&g_sq2[tid], s_sq[tid]);
    }
}

// ---------------- final: relu(affine2) on k-maxes ----------------
__global__ __launch_bounds__(256) void final_kernel(float* __restrict__ out) {
    int idx = blockIdx.x * 256 + threadIdx.x;
    int s = idx & (SS - 1);
    int c = (idx >> 10) & 127;
    int b = idx >> 17;
    float v = g_m2[(b << 10) + s][c];
    float m = fmaxf(fmaf(g_s2[c], v, g_t2[c]), 0.0f);
    out[XYZ_OUT + ((size_t)(b * 128 + c)) * SS + s] = m;
}

// ---------------- launch ----------------
extern "C" void kernel_launch(void* const* d_in, const int* in_sizes, int n_in,
                              void* d_out, int out_size) {
    const float* xyz  = (const float*)d_in[0];
    const float* feat = (const float*)d_in[1];
    const float* w0   = (const float*)d_in[2];
    const float* g0   = (const float*)d_in[4];
    const float* bt0  = (const float*)d_in[5];
    const float* w1   = (const float*)d_in[6];
    const float* g1   = (const float*)d_in[8];
    const float* bt1  = (const float*)d_in[9];
    const float* w2   = (const float*)d_in[10];
    const float* g2   = (const float*)d_in[12];
    const float* bt2  = (const float*)d_in[13];
    float* out = (float*)d_out;

    zero_kernel<<<1, 128>>>();                              // #1
    fps_kernel<<<BB, 256>>>(xyz, out);                      // #2
    ball_group_kernel<<<(BB * SS) / 8, 256>>>(xyz, feat);   // #3
    gram_kernel<<<512, 256>>>();                            // #4 <- ncu window (verify fix)
    stats0_kernel<<<1, 64>>>(w0, g0, bt0);                  // #5

    gemm1_kernel<<<POSN / 256, 256>>>(w0, w1);              // #6
    stats_kernel<1><<<1, 128>>>(g1, bt1);                   // #7

    gemm2_kernel<<<POSN / 256, 256>>>(w2);                  // #8
    stats_kernel<2><<<1, 128>>>(g2, bt2);                   // #9

    final_kernel<<<(BB * 128 * SS) / 256, 256>>>(out);      // #10
}

// round 16
// speedup vs baseline: 1.0813x; 1.0813x over previous
#include <cuda_runtime.h>

#define BB 16
#define NN 4096
#define SS 1024
#define KK 32
#define POSN (BB*SS*KK)          // 524288
#define NGRP (BB*SS)             // 16384
#define XYZ_OUT (BB*3*SS)        // 49152

typedef unsigned long long ull;

// ---------------- packed f32x2 helpers ----------------
union U2 { ull u; float2 f; };

__device__ __forceinline__ ull pack2(float lo, float hi) {
    U2 t; t.f.x = lo; t.f.y = hi; return t.u;
}
__device__ __forceinline__ void ffma2(ull& d, ull a, ull b) {
    asm("fma.rn.f32x2 %0, %1, %2, %0;" : "+l"(d) : "l"(a), "l"(b));
}
__device__ __forceinline__ ull add2(ull a, ull b) {
    ull r; asm("add.rn.f32x2 %0, %1, %2;" : "=l"(r) : "l"(a), "l"(b)); return r;
}
__device__ __forceinline__ ull mul2(ull a, ull b) {
    ull r; asm("mul.rn.f32x2 %0, %1, %2;" : "=l"(r) : "l"(a), "l"(b)); return r;
}
__device__ __forceinline__ ull max2(ull a, ull b) {
    U2 x, y, r; x.u = a; y.u = b;
    r.f.x = fmaxf(x.f.x, y.f.x); r.f.y = fmaxf(x.f.y, y.f.y);
    return r.u;
}
__device__ __forceinline__ ull min2(ull a, ull b) {
    U2 x, y, r; x.u = a; y.u = b;
    r.f.x = fminf(x.f.x, y.f.x); r.f.y = fminf(x.f.y, y.f.y);
    return r.u;
}
__device__ __forceinline__ ull umax64(ull a, ull b) { return a > b ? a : b; }

// ---------------- scratch ----------------
__device__ float g_newxyz[BB][SS][3];
__device__ float g_G[6][POSN];
__device__ float g_x1[64][POSN];
__device__ float g_m2[NGRP][128];
__device__ float g_gsum0[6], g_gram0[21];
__device__ float g_sum1[64], g_sq1[64];
__device__ float g_sum2[128], g_sq2[128];
__device__ float g_s0[64], g_t0[64];
__device__ float g_s1[64], g_t1[64];
__device__ float g_s2[128], g_t2[128];

// ---------------- tiny kernels ----------------
__global__ void zero_kernel() {
    int t = threadIdx.x;
    if (t < 64) { g_sum1[t] = 0.f; g_sq1[t] = 0.f; }
    if (t < 128) { g_sum2[t] = 0.f; g_sq2[t] = 0.f; }
    if (t < 6) g_gsum0[t] = 0.f;
    if (t < 21) g_gram0[t] = 0.f;
}

// ---------------- FPS: R15 version (tree tail) — UNCHANGED ----------------
__global__ __launch_bounds__(256) void fps_kernel(const float* __restrict__ xyz,
                                                  float* __restrict__ out) {
    __shared__ ull s_key[2][8];
    __shared__ int s_idx[SS];

    const int b = blockIdx.x;
    const int tid = threadIdx.x;
    const int w = tid >> 5, lane = tid & 31;
    const float* px = xyz + (size_t)b * 3 * NN;
    const float* py = px + NN;
    const float* pz = px + 2 * NN;

    const int base = tid * 16;
    ull X2[8], Y2[8], Z2[8], D2[8];
#pragma unroll
    for (int j = 0; j < 8; j++) {
        X2[j] = *(const ull*)(px + base + 2 * j);
        Y2[j] = *(const ull*)(py + base + 2 * j);
        Z2[j] = *(const ull*)(pz + base + 2 * j);
        D2[j] = pack2(1e10f, 1e10f);
    }

    int cur = 0;
    for (int it = 0; it < SS; it++) {
        if (tid == 0) s_idx[it] = cur;
        float cx = px[cur], cy = py[cur], cz = pz[cur];
        ull ncx = pack2(-cx, -cx), ncy = pack2(-cy, -cy), ncz = pack2(-cz, -cz);

        ull bm = pack2(-1.0f, -1.0f);
#pragma unroll
        for (int j = 0; j < 8; j++) {
            ull dx = add2(X2[j], ncx);
            ull dy = add2(Y2[j], ncy);
            ull dz = add2(Z2[j], ncz);
            ull t = mul2(dx, dx);
            ffma2(t, dy, dy);
            ffma2(t, dz, dz);
            D2[j] = min2(D2[j], t);
            bm = max2(bm, D2[j]);
        }
        U2 bu; bu.u = bm;
        float bv = fmaxf(bu.f.x, bu.f.y);
        unsigned wmx = __reduce_max_sync(0xffffffffu, __float_as_uint(bv));
        float wmax = __uint_as_float(wmx);
        int cand = 0x7fffffff;
#pragma unroll
        for (int j = 7; j >= 0; j--) {
            U2 d; d.u = D2[j];
            if (d.f.y == wmax) cand = base + 2 * j + 1;
            if (d.f.x == wmax) cand = base + 2 * j;
        }
        unsigned m = __ballot_sync(0xffffffffu, cand != 0x7fffffff);
        int widx = __shfl_sync(0xffffffffu, cand, __ffs(m) - 1);
        if (lane == 0)
            s_key[it & 1][w] = (((ull)wmx) << 32) | (unsigned)(~widx);
        __syncthreads();
        ull a0 = s_key[it & 1][0], a1 = s_key[it & 1][1];
        ull a2 = s_key[it & 1][2], a3 = s_key[it & 1][3];
        ull a4 = s_key[it & 1][4], a5 = s_key[it & 1][5];
        ull a6 = s_key[it & 1][6], a7 = s_key[it & 1][7];
        ull k01 = umax64(a0, a1), k23 = umax64(a2, a3);
        ull k45 = umax64(a4, a5), k67 = umax64(a6, a7);
        ull k03 = umax64(k01, k23), k47 = umax64(k45, k67);
        ull k = umax64(k03, k47);
        cur = (int)(~(unsigned)k);
    }

    for (int s = tid; s < SS; s += 256) {
        int i = s_idx[s];
        float cx = px[i], cy = py[i], cz = pz[i];
        g_newxyz[b][s][0] = cx; g_newxyz[b][s][1] = cy; g_newxyz[b][s][2] = cz;
        out[(size_t)b * 3 * SS + s]          = cx;
        out[(size_t)b * 3 * SS + SS + s]     = cy;
        out[(size_t)b * 3 * SS + 2 * SS + s] = cz;
    }
}

// ---------------- ball query + grouping: R13 2-chunk scan — UNCHANGED ----------------
__global__ __launch_bounds__(256) void ball_group_kernel(const float* __restrict__ xyz,
                                                         const float* __restrict__ feat) {
    __shared__ int nbr[8][KK];
    const int tid = threadIdx.x;
    const int w = tid >> 5, lane = tid & 31;
    const int gw = blockIdx.x * 8 + w;
    const int b = gw >> 10, s = gw & 1023;

    const float* px = xyz + (size_t)b * 3 * NN;
    const float* py = px + NN;
    const float* pz = px + 2 * NN;

    const float cx = g_newxyz[b][s][0];
    const float cy = g_newxyz[b][s][1];
    const float cz = g_newxyz[b][s][2];
    const float sn = __fadd_rn(__fadd_rn(__fmul_rn(cx, cx), __fmul_rn(cy, cy)),
                               __fmul_rn(cz, cz));

    int cnt = 0;
    for (int c0 = 0; c0 < NN && cnt < KK; c0 += 64) {
        int n0 = c0 + lane;
        int n1 = c0 + 32 + lane;
        float x0 = px[n0], y0 = py[n0], z0 = pz[n0];
        float x1 = px[n1], y1 = py[n1], z1 = pz[n1];
        float xn0 = __fadd_rn(__fadd_rn(__fmul_rn(x0, x0), __fmul_rn(y0, y0)),
                              __fmul_rn(z0, z0));
        float xn1 = __fadd_rn(__fadd_rn(__fmul_rn(x1, x1), __fmul_rn(y1, y1)),
                              __fmul_rn(z1, z1));
        float dt0 = __fadd_rn(__fadd_rn(__fmul_rn(cx, x0), __fmul_rn(cy, y0)),
                              __fmul_rn(cz, z0));
        float dt1 = __fadd_rn(__fadd_rn(__fmul_rn(cx, x1), __fmul_rn(cy, y1)),
                              __fmul_rn(cz, z1));
        float sqr0 = __fsub_rn(__fadd_rn(sn, xn0), __fmul_rn(2.0f, dt0));
        float sqr1 = __fsub_rn(__fadd_rn(sn, xn1), __fmul_rn(2.0f, dt1));
        bool in0 = !(sqr0 > 0.04f);
        bool in1 = !(sqr1 > 0.04f);
        unsigned m0 = __ballot_sync(0xffffffffu, in0);
        unsigned m1 = __ballot_sync(0xffffffffu, in1);
        if (in0) {
            int slot = cnt + __popc(m0 & ((1u << lane) - 1u));
            if (slot < KK) nbr[w][slot] = n0;
        }
        cnt += __popc(m0);
        if (in1) {
            int slot = cnt + __popc(m1 & ((1u << lane) - 1u));
            if (slot < KK) nbr[w][slot] = n1;
        }
        cnt += __popc(m1);
    }
    __syncwarp();
    int eff = cnt < KK ? cnt : KK;
    int first = nbr[w][0];
    int myn = (lane < eff) ? nbr[w][lane] : first;

    float gx = px[myn] - cx, gy = py[myn] - cy, gz = pz[myn] - cz;
    const float* f = feat + (size_t)b * 3 * NN;
    float f0 = f[myn], f1 = f[NN + myn], f2 = f[2 * NN + myn];

    size_t pos = ((size_t)gw) * KK + lane;
    g_G[0][pos] = gx; g_G[1][pos] = gy; g_G[2][pos] = gz;
    g_G[3][pos] = f0; g_G[4][pos] = f1; g_G[5][pos] = f2;
}

// ---------------- Gram: 256 blocks x 8 iters + BLOCK smem reduction ----------------
__global__ __launch_bounds__(256) void gram_kernel() {
    __shared__ float bs[8][27];
    const int tid = threadIdx.x;
    const int w = tid >> 5, lane = tid & 31;
    size_t p0 = (size_t)blockIdx.x * 2048 + tid;
    float S[6] = {0, 0, 0, 0, 0, 0};
    float G[21];
#pragma unroll
    for (int k = 0; k < 21; k++) G[k] = 0.f;

#pragma unroll
    for (int itn = 0; itn < 8; itn++) {
        size_t pos = p0 + (size_t)itn * 256;
        float g[6];
#pragma unroll
        for (int c = 0; c < 6; c++) g[c] = g_G[c][pos];
        int k = 0;
#pragma unroll
        for (int c = 0; c < 6; c++) {
            S[c] += g[c];
#pragma unroll
            for (int d = c; d < 6; d++) { G[k] = fmaf(g[c], g[d], G[k]); k++; }
        }
    }
#pragma unroll
    for (int o = 16; o > 0; o >>= 1) {
#pragma unroll
        for (int c = 0; c < 6; c++) S[c] += __shfl_xor_sync(0xffffffffu, S[c], o);
#pragma unroll
        for (int k = 0; k < 21; k++) G[k] += __shfl_xor_sync(0xffffffffu, G[k], o);
    }
    if (lane == 0) {
#pragma unroll
        for (int c = 0; c < 6; c++) bs[w][c] = S[c];
#pragma unroll
        for (int k = 0; k < 21; k++) bs[w][6 + k] = G[k];
    }
    __syncthreads();
    // one atomic per scalar per BLOCK (27 total) instead of per warp
    if (tid < 27) {
        float v = 0.f;
#pragma unroll
        for (int ww = 0; ww < 8; ww++) v += bs[ww][tid];
        if (tid < 6) atomicAdd(&g_gsum0[tid], v);
        else         atomicAdd(&g_gram0[tid - 6], v);
    }
}

// ---------------- stats0: BN affine from Gram quadratic form ----------------
__global__ void stats0_kernel(const float* __restrict__ W,
                              const float* __restrict__ gamma,
                              const float* __restrict__ beta) {
    int c = threadIdx.x;
    if (c >= 64) return;
    float w[6];
#pragma unroll
    for (int i = 0; i < 6; i++) w[i] = W[c * 6 + i];

    float sum = 0.f;
#pragma unroll
    for (int i = 0; i < 6; i++) sum = fmaf(w[i], g_gsum0[i], sum);

    float sq = 0.f;
    int k = 0;
#pragma unroll
    for (int i = 0; i < 6; i++)
#pragma unroll
        for (int j = i; j < 6; j++) {
            float coef = (i == j) ? w[i] * w[i] : 2.0f * w[i] * w[j];
            sq = fmaf(coef, g_gram0[k], sq);
            k++;
        }

    const float inv = 1.0f / (float)POSN;
    float mu = sum * inv;
    float var = fmaf(-mu, mu, sq * inv);
    if (var < 0.f) var = 0.f;
    float rs = 1.0f / sqrtf(var + 1e-5f);
    float sc = rs * gamma[c];
    g_s0[c] = sc;
    g_t0[c] = fmaf(-mu, sc, beta[c]);
}

// ---------------- stats (stages 1,2) ----------------
template <int STAGE>
__global__ void stats_kernel(const float* __restrict__ gamma, const float* __restrict__ beta) {
    constexpr int C = (STAGE == 2) ? 128 : 64;
    const float* sum = STAGE == 1 ? g_sum1 : g_sum2;
    const float* sq  = STAGE == 1 ? g_sq1  : g_sq2;
    float* Sv = STAGE == 1 ? g_s1 : g_s2;
    float* Tv = STAGE == 1 ? g_t1 : g_t2;
    int c = threadIdx.x;
    if (c < C) {
        const float inv = 1.0f / (float)POSN;
        float m = sum[c] * inv;
        float var = fmaf(-m, m, sq[c] * inv);
        if (var < 0.f) var = 0.f;
        float rs = 1.0f / sqrtf(var + 1e-5f);
        float sc = rs * gamma[c];
        Sv[c] = sc;
        Tv[c] = fmaf(-m, sc, beta[c]);
    }
}

// ---------------- gemm1: R12 version (LDS.64-direct weights) — UNCHANGED ----------------
__global__ __launch_bounds__(256) void gemm1_kernel(const float* __restrict__ W0,
                                                    const float* __restrict__ W1) {
    __shared__ __align__(16) float w0s[6 * 64];
    __shared__ __align__(16) float Wp[64 * 32];
    __shared__ float ss[64], tt[64];
    __shared__ float tile[8][32][33];
    __shared__ float s_sum[64], s_sq[64];
    const int tid = threadIdx.x;
    const int w = tid >> 5, lane = tid & 31;
    for (int e = tid; e < 384; e += 256) {
        int i = e >> 6, o = e & 63;
        w0s[e] = W0[o * 6 + i];
    }
    if (tid < 64) {
        ss[tid] = g_s0[tid]; tt[tid] = g_t0[tid];
        s_sum[tid] = 0.f; s_sq[tid] = 0.f;
    }
    __syncthreads();

    size_t pos = (size_t)blockIdx.x * 256 + tid;
    float g[6];
#pragma unroll
    for (int c = 0; c < 6; c++) g[c] = g_G[c][pos];

    ull acc0[32];
#pragma unroll
    for (int o2 = 0; o2 < 32; o2++) acc0[o2] = 0ull;
#pragma unroll
    for (int i = 0; i < 6; i++) {
        ull g2 = pack2(g[i], g[i]);
        const ull* wr = (const ull*)(w0s + i * 64);
#pragma unroll
        for (int o2 = 0; o2 < 32; o2++) ffma2(acc0[o2], wr[o2], g2);
    }
    float y[64];
#pragma unroll
    for (int o2 = 0; o2 < 32; o2++) {
        U2 u; u.u = acc0[o2];
        y[2 * o2]     = fmaxf(fmaf(ss[2 * o2],     u.f.x, tt[2 * o2]),     0.0f);
        y[2 * o2 + 1] = fmaxf(fmaf(ss[2 * o2 + 1], u.f.y, tt[2 * o2 + 1]), 0.0f);
    }

#pragma unroll 1
    for (int pass = 0; pass < 2; pass++) {
        __syncthreads();
        for (int e = tid; e < 2048; e += 256) {
            int i = e >> 5, o = e & 31;
            Wp[e] = W1[(pass * 32 + o) * 64 + i];
        }
        __syncthreads();

        ull acc2[16];
#pragma unroll
        for (int jp = 0; jp < 16; jp++) acc2[jp] = 0ull;
#pragma unroll 8
        for (int i = 0; i < 64; i++) {
            ull y2 = pack2(y[i], y[i]);
            const ull* wv = (const ull*)(Wp + i * 32);
#pragma unroll
            for (int jp = 0; jp < 16; jp++) ffma2(acc2[jp], wv[jp], y2);
        }
#pragma unroll
        for (int jp = 0; jp < 16; jp++) {
            U2 u; u.u = acc2[jp];
            int c0 = pass * 32 + 2 * jp;
            g_x1[c0][pos]     = u.f.x;
            g_x1[c0 + 1][pos] = u.f.y;
            tile[w][lane][2 * jp]     = u.f.x;
            tile[w][lane][2 * jp + 1] = u.f.y;
        }
        __syncwarp();
        if (lane < 16) {
            float sm0 = 0.f, sm1 = 0.f, q0 = 0.f, q1 = 0.f;
#pragma unroll 8
            for (int r = 0; r < 32; r++) {
                float v0 = tile[w][r][2 * lane];
                float v1 = tile[w][r][2 * lane + 1];
                sm0 += v0; q0 = fmaf(v0, v0, q0);
                sm1 += v1; q1 = fmaf(v1, v1, q1);
            }
            int c0 = pass * 32 + 2 * lane;
            atomicAdd(&s_sum[c0], sm0);     atomicAdd(&s_sum[c0 + 1], sm1);
            atomicAdd(&s_sq[c0], q0);       atomicAdd(&s_sq[c0 + 1], q1);
        }
        __syncwarp();
    }
    __syncthreads();
    if (tid < 64) {
        atomicAdd(&g_sum1[tid], s_sum[tid]);
        atomicAdd(&g_sq1[tid], s_sq[tid]);
    }
}

// ---------------- gemm2: R12 version (LDS.64-direct weights) — UNCHANGED ----------------
__global__ __launch_bounds__(256) void gemm2_kernel(const float* __restrict__ W) {
    __shared__ __align__(16) float Wp[64 * 32];
    __shared__ float ss[64], tt[64];
    __shared__ float tile[8][32][33];
    __shared__ float s_sum[128], s_sq[128];
    const int tid = threadIdx.x;
    const int w = tid >> 5, lane = tid & 31;
    if (tid < 64) { ss[tid] = g_s1[tid]; tt[tid] = g_t1[tid]; }
    if (tid < 128) { s_sum[tid] = 0.f; s_sq[tid] = 0.f; }
    __syncthreads();

    size_t pos = (size_t)blockIdx.x * 256 + tid;
    const int group = (int)(pos >> 5);
    float y[64];
#pragma unroll
    for (int i = 0; i < 64; i++)
        y[i] = fmaxf(fmaf(ss[i], g_x1[i][pos], tt[i]), 0.0f);

#pragma unroll 1
    for (int pass = 0; pass < 4; pass++) {
        __syncthreads();
        for (int e = tid; e < 2048; e += 256) {
            int i = e >> 5, o = e & 31;
            Wp[e] = W[(pass * 32 + o) * 64 + i];
        }
        __syncthreads();

        ull acc2[16];
#pragma unroll
        for (int jp = 0; jp < 16; jp++) acc2[jp] = 0ull;
#pragma unroll 8
        for (int i = 0; i < 64; i++) {
            ull y2 = pack2(y[i], y[i]);
            const ull* wv = (const ull*)(Wp + i * 32);
#pragma unroll
            for (int jp = 0; jp < 16; jp++) ffma2(acc2[jp], wv[jp], y2);
        }
#pragma unroll
        for (int jp = 0; jp < 16; jp++) {
            U2 u; u.u = acc2[jp];
            tile[w][lane][2 * jp]     = u.f.x;
            tile[w][lane][2 * jp + 1] = u.f.y;
        }
        __syncwarp();
        if (lane < 16) {
            float sm0 = 0.f, sm1 = 0.f, q0 = 0.f, q1 = 0.f;
            float mx0 = -1e30f, mx1 = -1e30f;
#pragma unroll 8
            for (int r = 0; r < 32; r++) {
                float v0 = tile[w][r][2 * lane];
                float v1 = tile[w][r][2 * lane + 1];
                sm0 += v0; q0 = fmaf(v0, v0, q0); mx0 = fmaxf(mx0, v0);
                sm1 += v1; q1 = fmaf(v1, v1, q1); mx1 = fmaxf(mx1, v1);
            }
            int c0 = pass * 32 + 2 * lane;
            atomicAdd(&s_sum[c0], sm0);     atomicAdd(&s_sum[c0 + 1], sm1);
            atomicAdd(&s_sq[c0], q0);       atomicAdd(&s_sq[c0 + 1], q1);
            *(ull*)&g_m2[group][c0] = pack2(mx0, mx1);
        }
        __syncwarp();
    }
    __syncthreads();
    if (tid < 128) {
        atomicAdd(&g_sum2[tid], s_sum[tid]);
        atomicAdd(&g_sq2[tid], s_sq[tid]);
    }
}

// ---------------- final: coalesced smem-transpose relu(affine2) ----------------
__global__ __launch_bounds__(256) void final_kernel(float* __restrict__ out) {
    __shared__ float tile[64][129];                 // 64 s x 128 c, padded
    const int tid = threadIdx.x;
    const int b = blockIdx.x >> 4;
    const int s0 = (blockIdx.x & 15) * 64;
    const float* src = &g_m2[(b << 10) + s0][0];
    // coalesced load: consecutive threads -> consecutive c
#pragma unroll
    for (int k = 0; k < 32; k++) {
        int e = tid + k * 256;                      // e in [0, 8192)
        int s = e >> 7, c = e & 127;
        tile[s][c] = src[e];
    }
    __syncthreads();
    // coalesced store: consecutive threads -> consecutive s (contiguous in out)
#pragma unroll
    for (int k = 0; k < 32; k++) {
        int e = tid + k * 256;
        int c = e >> 6, s = e & 63;                 // 128 c x 64 s
        float v = tile[s][c];
        float m = fmaxf(fmaf(g_s2[c], v, g_t2[c]), 0.0f);
        out[XYZ_OUT + ((size_t)(b * 128 + c)) * SS + s0 + s] = m;
    }
}

// ---------------- launch ----------------
extern "C" void kernel_launch(void* const* d_in, const int* in_sizes, int n_in,
                              void* d_out, int out_size) {
    const float* xyz  = (const float*)d_in[0];
    const float* feat = (const float*)d_in[1];
    const float* w0   = (const float*)d_in[2];
    const float* g0   = (const float*)d_in[4];
    const float* bt0  = (const float*)d_in[5];
    const float* w1   = (const float*)d_in[6];
    const float* g1   = (const float*)d_in[8];
    const float* bt1  = (const float*)d_in[9];
    const float* w2   = (const float*)d_in[10];
    const float* g2   = (const float*)d_in[12];
    const float* bt2  = (const float*)d_in[13];
    float* out = (float*)d_out;

    zero_kernel<<<1, 128>>>();                              // #1
    fps_kernel<<<BB, 256>>>(xyz, out);                      // #2
    ball_group_kernel<<<(BB * SS) / 8, 256>>>(xyz, feat);   // #3
    gram_kernel<<<256, 256>>>();                            // #4 <- ncu window (verify fix)
    stats0_kernel<<<1, 64>>>(w0, g0, bt0);                  // #5

    gemm1_kernel<<<POSN / 256, 256>>>(w0, w1);              // #6
    stats_kernel<1><<<1, 128>>>(g1, bt1);                   // #7

    gemm2_kernel<<<POSN / 256, 256>>>(w2);                  // #8
    stats_kernel<2><<<1, 128>>>(g2, bt2);                   // #9

    final_kernel<<<BB * 16, 256>>>(out);                    // #10
}

// round 17
// speedup vs baseline: 1.1227x; 1.0383x over previous
#include <cuda_runtime.h>

#define BB 16
#define NN 4096
#define SS 1024
#define KK 32
#define POSN (BB*SS*KK)          // 524288
#define NGRP (BB*SS)             // 16384
#define XYZ_OUT (BB*3*SS)        // 49152

typedef unsigned long long ull;

// ---------------- packed f32x2 helpers ----------------
union U2 { ull u; float2 f; };

__device__ __forceinline__ ull pack2(float lo, float hi) {
    U2 t; t.f.x = lo; t.f.y = hi; return t.u;
}
__device__ __forceinline__ void ffma2(ull& d, ull a, ull b) {
    asm("fma.rn.f32x2 %0, %1, %2, %0;" : "+l"(d) : "l"(a), "l"(b));
}
__device__ __forceinline__ ull add2(ull a, ull b) {
    ull r; asm("add.rn.f32x2 %0, %1, %2;" : "=l"(r) : "l"(a), "l"(b)); return r;
}
__device__ __forceinline__ ull mul2(ull a, ull b) {
    ull r; asm("mul.rn.f32x2 %0, %1, %2;" : "=l"(r) : "l"(a), "l"(b)); return r;
}
__device__ __forceinline__ ull max2(ull a, ull b) {
    U2 x, y, r; x.u = a; y.u = b;
    r.f.x = fmaxf(x.f.x, y.f.x); r.f.y = fmaxf(x.f.y, y.f.y);
    return r.u;
}
__device__ __forceinline__ ull min2(ull a, ull b) {
    U2 x, y, r; x.u = a; y.u = b;
    r.f.x = fminf(x.f.x, y.f.x); r.f.y = fminf(x.f.y, y.f.y);
    return r.u;
}
__device__ __forceinline__ ull umax64(ull a, ull b) { return a > b ? a : b; }

// ---------------- scratch ----------------
__device__ float g_newxyz[BB][SS][3];
__device__ float g_G[6][POSN];
__device__ float g_x1[64][POSN];
__device__ float g_m2[NGRP][128];
__device__ float g_gsum0[6], g_gram0[21];
__device__ float g_sum1[64], g_sq1[64];
__device__ float g_sum2[128], g_sq2[128];
__device__ float g_s0[64], g_t0[64];
__device__ float g_s1[64], g_t1[64];
__device__ float g_s2[128], g_t2[128];

// ---------------- tiny kernels ----------------
__global__ void zero_kernel() {
    int t = threadIdx.x;
    if (t < 64) { g_sum1[t] = 0.f; g_sq1[t] = 0.f; }
    if (t < 128) { g_sum2[t] = 0.f; g_sq2[t] = 0.f; }
    if (t < 6) g_gsum0[t] = 0.f;
    if (t < 21) g_gram0[t] = 0.f;
}

// ---------------- FPS: R15 version (tree tail) — UNCHANGED ----------------
__global__ __launch_bounds__(256) void fps_kernel(const float* __restrict__ xyz,
                                                  float* __restrict__ out) {
    __shared__ ull s_key[2][8];
    __shared__ int s_idx[SS];

    const int b = blockIdx.x;
    const int tid = threadIdx.x;
    const int w = tid >> 5, lane = tid & 31;
    const float* px = xyz + (size_t)b * 3 * NN;
    const float* py = px + NN;
    const float* pz = px + 2 * NN;

    const int base = tid * 16;
    ull X2[8], Y2[8], Z2[8], D2[8];
#pragma unroll
    for (int j = 0; j < 8; j++) {
        X2[j] = *(const ull*)(px + base + 2 * j);
        Y2[j] = *(const ull*)(py + base + 2 * j);
        Z2[j] = *(const ull*)(pz + base + 2 * j);
        D2[j] = pack2(1e10f, 1e10f);
    }

    int cur = 0;
    for (int it = 0; it < SS; it++) {
        if (tid == 0) s_idx[it] = cur;
        float cx = px[cur], cy = py[cur], cz = pz[cur];
        ull ncx = pack2(-cx, -cx), ncy = pack2(-cy, -cy), ncz = pack2(-cz, -cz);

        ull bm = pack2(-1.0f, -1.0f);
#pragma unroll
        for (int j = 0; j < 8; j++) {
            ull dx = add2(X2[j], ncx);
            ull dy = add2(Y2[j], ncy);
            ull dz = add2(Z2[j], ncz);
            ull t = mul2(dx, dx);
            ffma2(t, dy, dy);
            ffma2(t, dz, dz);
            D2[j] = min2(D2[j], t);
            bm = max2(bm, D2[j]);
        }
        U2 bu; bu.u = bm;
        float bv = fmaxf(bu.f.x, bu.f.y);
        unsigned wmx = __reduce_max_sync(0xffffffffu, __float_as_uint(bv));
        float wmax = __uint_as_float(wmx);
        int cand = 0x7fffffff;
#pragma unroll
        for (int j = 7; j >= 0; j--) {
            U2 d; d.u = D2[j];
            if (d.f.y == wmax) cand = base + 2 * j + 1;
            if (d.f.x == wmax) cand = base + 2 * j;
        }
        unsigned m = __ballot_sync(0xffffffffu, cand != 0x7fffffff);
        int widx = __shfl_sync(0xffffffffu, cand, __ffs(m) - 1);
        if (lane == 0)
            s_key[it & 1][w] = (((ull)wmx) << 32) | (unsigned)(~widx);
        __syncthreads();
        ull a0 = s_key[it & 1][0], a1 = s_key[it & 1][1];
        ull a2 = s_key[it & 1][2], a3 = s_key[it & 1][3];
        ull a4 = s_key[it & 1][4], a5 = s_key[it & 1][5];
        ull a6 = s_key[it & 1][6], a7 = s_key[it & 1][7];
        ull k01 = umax64(a0, a1), k23 = umax64(a2, a3);
        ull k45 = umax64(a4, a5), k67 = umax64(a6, a7);
        ull k03 = umax64(k01, k23), k47 = umax64(k45, k67);
        ull k = umax64(k03, k47);
        cur = (int)(~(unsigned)k);
    }

    for (int s = tid; s < SS; s += 256) {
        int i = s_idx[s];
        float cx = px[i], cy = py[i], cz = pz[i];
        g_newxyz[b][s][0] = cx; g_newxyz[b][s][1] = cy; g_newxyz[b][s][2] = cz;
        out[(size_t)b * 3 * SS + s]          = cx;
        out[(size_t)b * 3 * SS + SS + s]     = cy;
        out[(size_t)b * 3 * SS + 2 * SS + s] = cz;
    }
}

// ---------------- ball query + grouping: R13 2-chunk scan — UNCHANGED ----------------
__global__ __launch_bounds__(256) void ball_group_kernel(const float* __restrict__ xyz,
                                                         const float* __restrict__ feat) {
    __shared__ int nbr[8][KK];
    const int tid = threadIdx.x;
    const int w = tid >> 5, lane = tid & 31;
    const int gw = blockIdx.x * 8 + w;
    const int b = gw >> 10, s = gw & 1023;

    const float* px = xyz + (size_t)b * 3 * NN;
    const float* py = px + NN;
    const float* pz = px + 2 * NN;

    const float cx = g_newxyz[b][s][0];
    const float cy = g_newxyz[b][s][1];
    const float cz = g_newxyz[b][s][2];
    const float sn = __fadd_rn(__fadd_rn(__fmul_rn(cx, cx), __fmul_rn(cy, cy)),
                               __fmul_rn(cz, cz));

    int cnt = 0;
    for (int c0 = 0; c0 < NN && cnt < KK; c0 += 64) {
        int n0 = c0 + lane;
        int n1 = c0 + 32 + lane;
        float x0 = px[n0], y0 = py[n0], z0 = pz[n0];
        float x1 = px[n1], y1 = py[n1], z1 = pz[n1];
        float xn0 = __fadd_rn(__fadd_rn(__fmul_rn(x0, x0), __fmul_rn(y0, y0)),
                              __fmul_rn(z0, z0));
        float xn1 = __fadd_rn(__fadd_rn(__fmul_rn(x1, x1), __fmul_rn(y1, y1)),
                              __fmul_rn(z1, z1));
        float dt0 = __fadd_rn(__fadd_rn(__fmul_rn(cx, x0), __fmul_rn(cy, y0)),
                              __fmul_rn(cz, z0));
        float dt1 = __fadd_rn(__fadd_rn(__fmul_rn(cx, x1), __fmul_rn(cy, y1)),
                              __fmul_rn(cz, z1));
        float sqr0 = __fsub_rn(__fadd_rn(sn, xn0), __fmul_rn(2.0f, dt0));
        float sqr1 = __fsub_rn(__fadd_rn(sn, xn1), __fmul_rn(2.0f, dt1));
        bool in0 = !(sqr0 > 0.04f);
        bool in1 = !(sqr1 > 0.04f);
        unsigned m0 = __ballot_sync(0xffffffffu, in0);
        unsigned m1 = __ballot_sync(0xffffffffu, in1);
        if (in0) {
            int slot = cnt + __popc(m0 & ((1u << lane) - 1u));
            if (slot < KK) nbr[w][slot] = n0;
        }
        cnt += __popc(m0);
        if (in1) {
            int slot = cnt + __popc(m1 & ((1u << lane) - 1u));
            if (slot < KK) nbr[w][slot] = n1;
        }
        cnt += __popc(m1);
    }
    __syncwarp();
    int eff = cnt < KK ? cnt : KK;
    int first = nbr[w][0];
    int myn = (lane < eff) ? nbr[w][lane] : first;

    float gx = px[myn] - cx, gy = py[myn] - cy, gz = pz[myn] - cz;
    const float* f = feat + (size_t)b * 3 * NN;
    float f0 = f[myn], f1 = f[NN + myn], f2 = f[2 * NN + myn];

    size_t pos = ((size_t)gw) * KK + lane;
    g_G[0][pos] = gx; g_G[1][pos] = gy; g_G[2][pos] = gz;
    g_G[3][pos] = f0; g_G[4][pos] = f1; g_G[5][pos] = f2;
}

// ---------------- Gram: R16 version (block-reduced atomics, measured 8.7us) ----------------
__global__ __launch_bounds__(256) void gram_kernel() {
    __shared__ float bs[8][27];
    const int tid = threadIdx.x;
    const int w = tid >> 5, lane = tid & 31;
    size_t p0 = (size_t)blockIdx.x * 2048 + tid;
    float S[6] = {0, 0, 0, 0, 0, 0};
    float G[21];
#pragma unroll
    for (int k = 0; k < 21; k++) G[k] = 0.f;

#pragma unroll
    for (int itn = 0; itn < 8; itn++) {
        size_t pos = p0 + (size_t)itn * 256;
        float g[6];
#pragma unroll
        for (int c = 0; c < 6; c++) g[c] = g_G[c][pos];
        int k = 0;
#pragma unroll
        for (int c = 0; c < 6; c++) {
            S[c] += g[c];
#pragma unroll
            for (int d = c; d < 6; d++) { G[k] = fmaf(g[c], g[d], G[k]); k++; }
        }
    }
#pragma unroll
    for (int o = 16; o > 0; o >>= 1) {
#pragma unroll
        for (int c = 0; c < 6; c++) S[c] += __shfl_xor_sync(0xffffffffu, S[c], o);
#pragma unroll
        for (int k = 0; k < 21; k++) G[k] += __shfl_xor_sync(0xffffffffu, G[k], o);
    }
    if (lane == 0) {
#pragma unroll
        for (int c = 0; c < 6; c++) bs[w][c] = S[c];
#pragma unroll
        for (int k = 0; k < 21; k++) bs[w][6 + k] = G[k];
    }
    __syncthreads();
    if (tid < 27) {
        float v = 0.f;
#pragma unroll
        for (int ww = 0; ww < 8; ww++) v += bs[ww][tid];
        if (tid < 6) atomicAdd(&g_gsum0[tid], v);
        else         atomicAdd(&g_gram0[tid - 6], v);
    }
}

// ---------------- stats0: BN affine from Gram quadratic form ----------------
__global__ void stats0_kernel(const float* __restrict__ W,
                              const float* __restrict__ gamma,
                              const float* __restrict__ beta) {
    int c = threadIdx.x;
    if (c >= 64) return;
    float w[6];
#pragma unroll
    for (int i = 0; i < 6; i++) w[i] = W[c * 6 + i];

    float sum = 0.f;
#pragma unroll
    for (int i = 0; i < 6; i++) sum = fmaf(w[i], g_gsum0[i], sum);

    float sq = 0.f;
    int k = 0;
#pragma unroll
    for (int i = 0; i < 6; i++)
#pragma unroll
        for (int j = i; j < 6; j++) {
            float coef = (i == j) ? w[i] * w[i] : 2.0f * w[i] * w[j];
            sq = fmaf(coef, g_gram0[k], sq);
            k++;
        }

    const float inv = 1.0f / (float)POSN;
    float mu = sum * inv;
    float var = fmaf(-mu, mu, sq * inv);
    if (var < 0.f) var = 0.f;
    float rs = 1.0f / sqrtf(var + 1e-5f);
    float sc = rs * gamma[c];
    g_s0[c] = sc;
    g_t0[c] = fmaf(-mu, sc, beta[c]);
}

// ---------------- stats (stages 1,2) ----------------
template <int STAGE>
__global__ void stats_kernel(const float* __restrict__ gamma, const float* __restrict__ beta) {
    constexpr int C = (STAGE == 2) ? 128 : 64;
    const float* sum = STAGE == 1 ? g_sum1 : g_sum2;
    const float* sq  = STAGE == 1 ? g_sq1  : g_sq2;
    float* Sv = STAGE == 1 ? g_s1 : g_s2;
    float* Tv = STAGE == 1 ? g_t1 : g_t2;
    int c = threadIdx.x;
    if (c < C) {
        const float inv = 1.0f / (float)POSN;
        float m = sum[c] * inv;
        float var = fmaf(-m, m, sq[c] * inv);
        if (var < 0.f) var = 0.f;
        float rs = 1.0f / sqrtf(var + 1e-5f);
        float sc = rs * gamma[c];
        Sv[c] = sc;
        Tv[c] = fmaf(-m, sc, beta[c]);
    }
}

// ---------------- gemm1: R12 body, occupancy 3 CTAs/SM (the experiment) ----------------
__global__ __launch_bounds__(256, 3) void gemm1_kernel(const float* __restrict__ W0,
                                                       const float* __restrict__ W1) {
    __shared__ __align__(16) float w0s[6 * 64];
    __shared__ __align__(16) float Wp[64 * 32];
    __shared__ float ss[64], tt[64];
    __shared__ float tile[8][32][33];
    __shared__ float s_sum[64], s_sq[64];
    const int tid = threadIdx.x;
    const int w = tid >> 5, lane = tid & 31;
    for (int e = tid; e < 384; e += 256) {
        int i = e >> 6, o = e & 63;
        w0s[e] = W0[o * 6 + i];
    }
    if (tid < 64) {
        ss[tid] = g_s0[tid]; tt[tid] = g_t0[tid];
        s_sum[tid] = 0.f; s_sq[tid] = 0.f;
    }
    __syncthreads();

    size_t pos = (size_t)blockIdx.x * 256 + tid;
    float g[6];
#pragma unroll
    for (int c = 0; c < 6; c++) g[c] = g_G[c][pos];

    ull acc0[32];
#pragma unroll
    for (int o2 = 0; o2 < 32; o2++) acc0[o2] = 0ull;
#pragma unroll
    for (int i = 0; i < 6; i++) {
        ull g2 = pack2(g[i], g[i]);
        const ull* wr = (const ull*)(w0s + i * 64);
#pragma unroll
        for (int o2 = 0; o2 < 32; o2++) ffma2(acc0[o2], wr[o2], g2);
    }
    float y[64];
#pragma unroll
    for (int o2 = 0; o2 < 32; o2++) {
        U2 u; u.u = acc0[o2];
        y[2 * o2]     = fmaxf(fmaf(ss[2 * o2],     u.f.x, tt[2 * o2]),     0.0f);
        y[2 * o2 + 1] = fmaxf(fmaf(ss[2 * o2 + 1], u.f.y, tt[2 * o2 + 1]), 0.0f);
    }

#pragma unroll 1
    for (int pass = 0; pass < 2; pass++) {
        __syncthreads();
        for (int e = tid; e < 2048; e += 256) {
            int i = e >> 5, o = e & 31;
            Wp[e] = W1[(pass * 32 + o) * 64 + i];
        }
        __syncthreads();

        ull acc2[16];
#pragma unroll
        for (int jp = 0; jp < 16; jp++) acc2[jp] = 0ull;
#pragma unroll 8
        for (int i = 0; i < 64; i++) {
            ull y2 = pack2(y[i], y[i]);
            const ull* wv = (const ull*)(Wp + i * 32);
#pragma unroll
            for (int jp = 0; jp < 16; jp++) ffma2(acc2[jp], wv[jp], y2);
        }
#pragma unroll
        for (int jp = 0; jp < 16; jp++) {
            U2 u; u.u = acc2[jp];
            int c0 = pass * 32 + 2 * jp;
            g_x1[c0][pos]     = u.f.x;
            g_x1[c0 + 1][pos] = u.f.y;
            tile[w][lane][2 * jp]     = u.f.x;
            tile[w][lane][2 * jp + 1] = u.f.y;
        }
        __syncwarp();
        if (lane < 16) {
            float sm0 = 0.f, sm1 = 0.f, q0 = 0.f, q1 = 0.f;
#pragma unroll 8
            for (int r = 0; r < 32; r++) {
                float v0 = tile[w][r][2 * lane];
                float v1 = tile[w][r][2 * lane + 1];
                sm0 += v0; q0 = fmaf(v0, v0, q0);
                sm1 += v1; q1 = fmaf(v1, v1, q1);
            }
            int c0 = pass * 32 + 2 * lane;
            atomicAdd(&s_sum[c0], sm0);     atomicAdd(&s_sum[c0 + 1], sm1);
            atomicAdd(&s_sq[c0], q0);       atomicAdd(&s_sq[c0 + 1], q1);
        }
        __syncwarp();
    }
    __syncthreads();
    if (tid < 64) {
        atomicAdd(&g_sum1[tid], s_sum[tid]);
        atomicAdd(&g_sq1[tid], s_sq[tid]);
    }
}

// ---------------- gemm2: R12 body, occupancy 3 CTAs/SM (the experiment) ----------------
__global__ __launch_bounds__(256, 3) void gemm2_kernel(const float* __restrict__ W) {
    __shared__ __align__(16) float Wp[64 * 32];
    __shared__ float ss[64], tt[64];
    __shared__ float tile[8][32][33];
    __shared__ float s_sum[128], s_sq[128];
    const int tid = threadIdx.x;
    const int w = tid >> 5, lane = tid & 31;
    if (tid < 64) { ss[tid] = g_s1[tid]; tt[tid] = g_t1[tid]; }
    if (tid < 128) { s_sum[tid] = 0.f; s_sq[tid] = 0.f; }
    __syncthreads();

    size_t pos = (size_t)blockIdx.x * 256 + tid;
    const int group = (int)(pos >> 5);
    float y[64];
#pragma unroll
    for (int i = 0; i < 64; i++)
        y[i] = fmaxf(fmaf(ss[i], g_x1[i][pos], tt[i]), 0.0f);

#pragma unroll 1
    for (int pass = 0; pass < 4; pass++) {
        __syncthreads();
        for (int e = tid; e < 2048; e += 256) {
            int i = e >> 5, o = e & 31;
            Wp[e] = W[(pass * 32 + o) * 64 + i];
        }
        __syncthreads();

        ull acc2[16];
#pragma unroll
        for (int jp = 0; jp < 16; jp++) acc2[jp] = 0ull;
#pragma unroll 8
        for (int i = 0; i < 64; i++) {
            ull y2 = pack2(y[i], y[i]);
            const ull* wv = (const ull*)(Wp + i * 32);
#pragma unroll
            for (int jp = 0; jp < 16; jp++) ffma2(acc2[jp], wv[jp], y2);
        }
#pragma unroll
        for (int jp = 0; jp < 16; jp++) {
            U2 u; u.u = acc2[jp];
            tile[w][lane][2 * jp]     = u.f.x;
            tile[w][lane][2 * jp + 1] = u.f.y;
        }
        __syncwarp();
        if (lane < 16) {
            float sm0 = 0.f, sm1 = 0.f, q0 = 0.f, q1 = 0.f;
            float mx0 = -1e30f, mx1 = -1e30f;
#pragma unroll 8
            for (int r = 0; r < 32; r++) {
                float v0 = tile[w][r][2 * lane];
                float v1 = tile[w][r][2 * lane + 1];
                sm0 += v0; q0 = fmaf(v0, v0, q0); mx0 = fmaxf(mx0, v0);
                sm1 += v1; q1 = fmaf(v1, v1, q1); mx1 = fmaxf(mx1, v1);
            }
            int c0 = pass * 32 + 2 * lane;
            atomicAdd(&s_sum[c0], sm0);     atomicAdd(&s_sum[c0 + 1], sm1);
            atomicAdd(&s_sq[c0], q0);       atomicAdd(&s_sq[c0 + 1], q1);
            *(ull*)&g_m2[group][c0] = pack2(mx0, mx1);
        }
        __syncwarp();
    }
    __syncthreads();
    if (tid < 128) {
        atomicAdd(&g_sum2[tid], s_sum[tid]);
        atomicAdd(&g_sq2[tid], s_sq[tid]);
    }
}

// ---------------- final: R16 coalesced smem-transpose — UNCHANGED ----------------
__global__ __launch_bounds__(256) void final_kernel(float* __restrict__ out) {
    __shared__ float tile[64][129];
    const int tid = threadIdx.x;
    const int b = blockIdx.x >> 4;
    const int s0 = (blockIdx.x & 15) * 64;
    const float* src = &g_m2[(b << 10) + s0][0];
#pragma unroll
    for (int k = 0; k < 32; k++) {
        int e = tid + k * 256;
        int s = e >> 7, c = e & 127;
        tile[s][c] = src[e];
    }
    __syncthreads();
#pragma unroll
    for (int k = 0; k < 32; k++) {
        int e = tid + k * 256;
        int c = e >> 6, s = e & 63;
        float v = tile[s][c];
        float m = fmaxf(fmaf(g_s2[c], v, g_t2[c]), 0.0f);
        out[XYZ_OUT + ((size_t)(b * 128 + c)) * SS + s0 + s] = m;
    }
}

// ---------------- launch ----------------
extern "C" void kernel_launch(void* const* d_in, const int* in_sizes, int n_in,
                              void* d_out, int out_size) {
    const float* xyz  = (const float*)d_in[0];
    const float* feat = (const float*)d_in[1];
    const float* w0   = (const float*)d_in[2];
    const float* g0   = (const float*)d_in[4];
    const float* bt0  = (const float*)d_in[5];
    const float* w1   = (const float*)d_in[6];
    const float* g1   = (const float*)d_in[8];
    const float* bt1  = (const float*)d_in[9];
    const float* w2   = (const float*)d_in[10];
    const float* g2   = (const float*)d_in[12];
    const float* bt2  = (const float*)d_in[13];
    float* out = (float*)d_out;

    zero_kernel<<<1, 128>>>();                              // #1
    fps_kernel<<<BB, 256>>>(xyz, out);                      // #2
    ball_group_kernel<<<(BB * SS) / 8, 256>>>(xyz, feat);   // #3
    gram_kernel<<<256, 256>>>();                            // #4 <- ncu window
    stats0_kernel<<<1, 64>>>(w0, g0, bt0);                  // #5

    gemm1_kernel<<<POSN / 256, 256>>>(w0, w1);              // #6
    stats_kernel<1><<<1, 128>>>(g1, bt1);                   // #7

    gemm2_kernel<<<POSN / 256, 256>>>(w2);                  // #8
    stats_kernel<2><<<1, 128>>>(g2, bt2);                   // #9

    final_kernel<<<BB * 16, 256>>>(out);                    // #10
}